// round 5
// baseline (speedup 1.0000x reference)
#include <cuda_runtime.h>

#define T_STEPS 512
#define BATCH   4096

__device__ __align__(16) float g_h2[T_STEPS * 16];

typedef unsigned long long ull;

__device__ __forceinline__ ull ffma2(ull a, ull b, ull c) {
    ull d; asm("fma.rn.f32x2 %0, %1, %2, %3;" : "=l"(d) : "l"(a), "l"(b), "l"(c)); return d;
}
__device__ __forceinline__ ull fadd2(ull a, ull b) {
    ull d; asm("add.rn.f32x2 %0, %1, %2;" : "=l"(d) : "l"(a), "l"(b)); return d;
}
__device__ __forceinline__ float hsum2(ull a) {
    float lo, hi; asm("mov.b64 {%0, %1}, %2;" : "=f"(lo), "=f"(hi) : "l"(a)); return lo + hi;
}
__device__ __forceinline__ ull pack2(float lo, float hi) {
    ull d; asm("mov.b64 %0, {%1, %2};" : "=l"(d) : "f"(lo), "f"(hi)); return d;
}
__device__ __forceinline__ float tanhapx(float x) {
    float y; asm("tanh.approx.f32 %0, %1;" : "=f"(y) : "f"(x)); return y;
}
// sigmoid(x) = 0.5*tanh(0.5x) + 0.5
__device__ __forceinline__ float sigapx(float x) {
    return fmaf(0.5f, tanhapx(0.5f * x), 0.5f);
}

// 96 threads, 3 warps:
//   warp0: layer0, gate-pair scheme (hi=0:{i,g}, hi=1:{f,o}), 16-wide dots.
//   warp1: layer1 gates {i (hi=0), g (hi=1)}, 32-wide dots over [h0|h1].
//   warp2: layer1 gates {f (hi=0), o (hi=1)}, 32-wide dots; ships f,o via smem.
// Layer1 runs one step behind layer0 (software pipeline). One block-wide
// barrier (h exchange) + one 64-thread sub-barrier (f,o handoff) per iter.
__global__ void __launch_bounds__(96, 1) lstm_recur_kernel(
    const float* __restrict__ x,
    const float* __restrict__ Wih0, const float* __restrict__ Whh0,
    const float* __restrict__ bih0, const float* __restrict__ bhh0,
    const float* __restrict__ Wih1, const float* __restrict__ Whh1,
    const float* __restrict__ bih1, const float* __restrict__ bhh1)
{
    __shared__ float x_sh[T_STEPS];
    __shared__ __align__(16) float hbuf[2][32];   // [parity][ h0(16) | h1(16) ]
    __shared__ float fobuf[32];                   // [u*2 + {0:f,1:o}]
    const int tid  = threadIdx.x;
    const int w    = tid >> 5;
    const int lane = tid & 31;
    const int u    = lane & 15;
    const int hi   = lane >> 4;

    // stage x[:, BATCH-1, 0]
#pragma unroll
    for (int r = 0; r < 6; r++) {
        const int idx = tid + 96 * r;
        if (idx < T_STEPS) x_sh[idx] = x[idx * BATCH + (BATCH - 1)];
    }
    if (tid < 32) { hbuf[0][tid] = 0.0f; hbuf[1][tid] = 0.0f; }

    // ---- per-lane weights ----
    ull WA[8], WB[8];          // warp0: two 16-wide gate rows
    ull W1v[16];               // warps1/2: one 32-wide gate row [Wih1 | Whh1]
    float biasA = 0.f, biasB = 0.f, wxA = 0.f, wxB = 0.f, bias1 = 0.f;
    // activation params for the single-gate warps and warp0's B gate
    float sB, pmB, paB;        // warp0 gate B: hi=0 -> tanh(g), hi=1 -> sigmoid(o)
    float s1, pm1, pa1;        // warps1/2 gate: tanh for g, sigmoid otherwise

    if (w == 0) {
        const int gA = hi;                       // i or f
        const int gB = hi + 2;                   // g or o
        const int giA = gA * 16 + u, giB = gB * 16 + u;
        const ull* Wp = (const ull*)Whh0;
#pragma unroll
        for (int k = 0; k < 8; k++) {
            WA[k] = Wp[giA * 8 + k];
            WB[k] = Wp[giB * 8 + k];
        }
        biasA = bih0[giA] + bhh0[giA];  biasB = bih0[giB] + bhh0[giB];
        wxA   = Wih0[giA];              wxB   = Wih0[giB];
        sB  = (hi == 0) ? 1.0f : 0.5f;
        pmB = (hi == 0) ? 1.0f : 0.5f;
        paB = (hi == 0) ? 0.0f : 0.5f;
        s1 = pm1 = pa1 = 0.f;
    } else {
        // warp1: hi=0 -> i, hi=1 -> g ; warp2: hi=0 -> f, hi=1 -> o
        const int g = (w == 1) ? ((hi == 0) ? 0 : 2) : ((hi == 0) ? 1 : 3);
        const int gi = g * 16 + u;
        const ull* Wi = (const ull*)Wih1;
        const ull* Wh = (const ull*)Whh1;
#pragma unroll
        for (int k = 0; k < 8; k++) {
            W1v[k]     = Wi[gi * 8 + k];
            W1v[8 + k] = Wh[gi * 8 + k];
        }
        bias1 = bih1[gi] + bhh1[gi];
        const bool isg = (w == 1) && (hi == 1);  // tanh gate
        s1  = isg ? 1.0f : 0.5f;
        pm1 = isg ? 1.0f : 0.5f;
        pa1 = isg ? 0.0f : 0.5f;
        sB = pmB = paB = 0.f;
    }

    float h = 0.0f, c = 0.0f;

#pragma unroll 2
    for (int i = 0; i <= T_STEPS; i++) {
        __syncthreads();   // publishes hbuf[i&1] = [h0[i-1] | h1[i-2]]
        const float* hb = hbuf[i & 1];

        if (w == 0) {
            // ---- layer0, step i ----
            const float xv = x_sh[(i < T_STEPS) ? i : 0];
            ull op[8];
            const ulonglong2* hp = (const ulonglong2*)hb;
#pragma unroll
            for (int j = 0; j < 4; j++) {
                ulonglong2 t2 = hp[j];
                op[2 * j] = t2.x; op[2 * j + 1] = t2.y;
            }
            ull a0 = ffma2(WA[0], op[0], pack2(fmaf(wxA, xv, biasA), 0.f));
            ull a1 = ffma2(WA[1], op[1], 0ull);
            ull a2 = ffma2(WA[2], op[2], 0ull);
            ull a3 = ffma2(WA[3], op[3], 0ull);
            ull b0 = ffma2(WB[0], op[0], pack2(fmaf(wxB, xv, biasB), 0.f));
            ull b1 = ffma2(WB[1], op[1], 0ull);
            ull b2 = ffma2(WB[2], op[2], 0ull);
            ull b3 = ffma2(WB[3], op[3], 0ull);
            a0 = ffma2(WA[4], op[4], a0); a1 = ffma2(WA[5], op[5], a1);
            a2 = ffma2(WA[6], op[6], a2); a3 = ffma2(WA[7], op[7], a3);
            b0 = ffma2(WB[4], op[4], b0); b1 = ffma2(WB[5], op[5], b1);
            b2 = ffma2(WB[6], op[6], b2); b3 = ffma2(WB[7], op[7], b3);
            const float aA = hsum2(fadd2(fadd2(a0, a1), fadd2(a2, a3)));
            const float aB = hsum2(fadd2(fadd2(b0, b1), fadd2(b2, b3)));

            const float vA = sigapx(aA);                       // i or f
            const float vB = fmaf(pmB, tanhapx(sB * aB), paB); // g or o
            const float fv = __shfl_sync(0xffffffffu, vA, lane | 16);
            const float ov = __shfl_sync(0xffffffffu, vB, lane | 16);
            if (hi == 0 && i < T_STEPS) {
                c = fmaf(fv, c, vA * vB);
                h = ov * tanhapx(c);
                hbuf[(i + 1) & 1][u] = h;
            }
        } else {
            // ---- layer1, step i-1 ----
            ull op[16];
            const ulonglong2* hp = (const ulonglong2*)hb;
#pragma unroll
            for (int j = 0; j < 8; j++) {
                ulonglong2 t2 = hp[j];
                op[2 * j] = t2.x; op[2 * j + 1] = t2.y;
            }
            ull a0 = ffma2(W1v[0], op[0], pack2(bias1, 0.f));
            ull a1 = ffma2(W1v[1], op[1], 0ull);
            ull a2 = ffma2(W1v[2], op[2], 0ull);
            ull a3 = ffma2(W1v[3], op[3], 0ull);
#pragma unroll
            for (int k = 4; k < 16; k += 4) {
                a0 = ffma2(W1v[k    ], op[k    ], a0);
                a1 = ffma2(W1v[k + 1], op[k + 1], a1);
                a2 = ffma2(W1v[k + 2], op[k + 2], a2);
                a3 = ffma2(W1v[k + 3], op[k + 3], a3);
            }
            const float a = hsum2(fadd2(fadd2(a0, a1), fadd2(a2, a3)));
            const float v = fmaf(pm1, tanhapx(s1 * a), pa1);

            if (w == 2) {
                fobuf[2 * u + hi] = v;        // f -> even, o -> odd (conflict-free)
                asm volatile("bar.sync 1, 64;" ::: "memory");
            } else {
                asm volatile("bar.sync 1, 64;" ::: "memory");
                const float gv = __shfl_sync(0xffffffffu, v, lane | 16);
                if (hi == 0 && i >= 1) {
                    const float2 fo = *(const float2*)&fobuf[2 * u];
                    c = fmaf(fo.x, c, v * gv);
                    h = fo.y * tanhapx(c);
                    hbuf[(i + 1) & 1][16 + u] = h;
                    g_h2[(i - 1) * 16 + u] = h;
                }
            }
        }
    }
}

// MLP 16 -> 64 (relu) -> 32 (relu) -> 1. One warp per timestep.
__global__ void __launch_bounds__(32) mlp_kernel(
    const float* __restrict__ W1, const float* __restrict__ b1,
    const float* __restrict__ W2, const float* __restrict__ b2,
    const float* __restrict__ W3, const float* __restrict__ b3,
    float* __restrict__ out)
{
    __shared__ __align__(16) float z1sh[64];
    const int t = blockIdx.x, lane = threadIdx.x;

    const float4* hp = (const float4*)(g_h2 + t * 16);
    const float4 h4[4] = { hp[0], hp[1], hp[2], hp[3] };

    float acc0 = b1[lane], acc1 = b1[lane + 32];
    const float4* w1a = (const float4*)(W1 + lane * 16);
    const float4* w1b = (const float4*)(W1 + (lane + 32) * 16);
#pragma unroll
    for (int q = 0; q < 4; q++) {
        const float4 wa = w1a[q], wb = w1b[q], hq = h4[q];
        acc0 = fmaf(wa.x, hq.x, acc0); acc0 = fmaf(wa.y, hq.y, acc0);
        acc0 = fmaf(wa.z, hq.z, acc0); acc0 = fmaf(wa.w, hq.w, acc0);
        acc1 = fmaf(wb.x, hq.x, acc1); acc1 = fmaf(wb.y, hq.y, acc1);
        acc1 = fmaf(wb.z, hq.z, acc1); acc1 = fmaf(wb.w, hq.w, acc1);
    }
    z1sh[lane]      = fmaxf(acc0, 0.0f);
    z1sh[lane + 32] = fmaxf(acc1, 0.0f);
    __syncwarp();

    float a2 = b2[lane];
    const float4* w2p = (const float4*)(W2 + lane * 64);
    const float4* z1p = (const float4*)z1sh;
#pragma unroll
    for (int q = 0; q < 16; q++) {
        const float4 wv = w2p[q], zv = z1p[q];
        a2 = fmaf(wv.x, zv.x, a2); a2 = fmaf(wv.y, zv.y, a2);
        a2 = fmaf(wv.z, zv.z, a2); a2 = fmaf(wv.w, zv.w, a2);
    }
    float v = fmaxf(a2, 0.0f) * W3[lane];
#pragma unroll
    for (int off = 16; off; off >>= 1)
        v += __shfl_xor_sync(0xffffffffu, v, off);
    if (lane == 0) out[t] = v + b3[0];
}

extern "C" void kernel_launch(void* const* d_in, const int* in_sizes, int n_in,
                              void* d_out, int out_size)
{
    const float* x    = (const float*)d_in[0];
    const float* Wih0 = (const float*)d_in[1];
    const float* Whh0 = (const float*)d_in[2];
    const float* bih0 = (const float*)d_in[3];
    const float* bhh0 = (const float*)d_in[4];
    const float* Wih1 = (const float*)d_in[5];
    const float* Whh1 = (const float*)d_in[6];
    const float* bih1 = (const float*)d_in[7];
    const float* bhh1 = (const float*)d_in[8];
    const float* W1   = (const float*)d_in[9];
    const float* b1   = (const float*)d_in[10];
    const float* W2   = (const float*)d_in[11];
    const float* b2   = (const float*)d_in[12];
    const float* W3   = (const float*)d_in[13];
    const float* b3   = (const float*)d_in[14];
    float* out = (float*)d_out;

    lstm_recur_kernel<<<1, 96>>>(x, Wih0, Whh0, bih0, bhh0,
                                 Wih1, Whh1, bih1, bhh1);
    mlp_kernel<<<T_STEPS, 32>>>(W1, b1, W2, b2, W3, b3, out);
}

// round 6
// speedup vs baseline: 1.7461x; 1.7461x over previous
#include <cuda_runtime.h>

#define T_STEPS 512
#define BATCH   4096

__device__ __align__(16) float g_h2[T_STEPS * 16];

typedef unsigned long long ull;

__device__ __forceinline__ ull ffma2(ull a, ull b, ull c) {
    ull d; asm("fma.rn.f32x2 %0, %1, %2, %3;" : "=l"(d) : "l"(a), "l"(b), "l"(c)); return d;
}
__device__ __forceinline__ ull fadd2(ull a, ull b) {
    ull d; asm("add.rn.f32x2 %0, %1, %2;" : "=l"(d) : "l"(a), "l"(b)); return d;
}
__device__ __forceinline__ float hsum2(ull a) {
    float lo, hi; asm("mov.b64 {%0, %1}, %2;" : "=f"(lo), "=f"(hi) : "l"(a)); return lo + hi;
}
__device__ __forceinline__ ull pack2(float lo, float hi) {
    ull d; asm("mov.b64 %0, {%1, %2};" : "=l"(d) : "f"(lo), "f"(hi)); return d;
}
__device__ __forceinline__ float tanhapx(float x) {
    float y; asm("tanh.approx.f32 %0, %1;" : "=f"(y) : "f"(x)); return y;
}
__device__ __forceinline__ float sigapx(float x) {       // 0.5*tanh(x/2)+0.5
    return fmaf(0.5f, tanhapx(0.5f * x), 0.5f);
}

// 96 threads, 3 warps, ONE __syncthreads per iteration (all cross-warp data
// rides parity-double-buffered smem published at that barrier):
//   warp0: layer0 step i        — gates over h0[i-1]           (16-wide dots)
//   warp2: z[i-1] = Wih1*h0[i-1] + bias1                       (16-wide dots)
//   warp1: layer1 step i-2      — gates = z[i-2] + Whh1*h1[i-3] (16-wide dots)
// Lane scheme per warp: lane=(u, hi); gate A = hi ({i,f}, sigmoid),
// gate B = hi+2 ({g,o}; g=tanh, o=sigmoid). hi=0 lanes own (c,h) of unit u.
__global__ void __launch_bounds__(96, 1) lstm_recur_kernel(
    const float* __restrict__ x,
    const float* __restrict__ Wih0, const float* __restrict__ Whh0,
    const float* __restrict__ bih0, const float* __restrict__ bhh0,
    const float* __restrict__ Wih1, const float* __restrict__ Whh1,
    const float* __restrict__ bih1, const float* __restrict__ bhh1)
{
    __shared__ float x_sh[T_STEPS];
    __shared__ __align__(16) float hbuf[2][32];   // [parity][ h0(16) | h1(16) ]
    __shared__ __align__(16) float zbuf[2][64];   // [parity][ g*16 + u ]
    const int tid  = threadIdx.x;
    const int w    = tid >> 5;
    const int lane = tid & 31;
    const int u    = lane & 15;
    const int hi   = lane >> 4;

    // stage x[:, BATCH-1, 0]
#pragma unroll
    for (int r = 0; r < 6; r++) {
        const int idx = tid + 96 * r;
        if (idx < T_STEPS) x_sh[idx] = x[idx * BATCH + (BATCH - 1)];
    }
    if (tid < 64) { hbuf[0][tid & 31] = 0.0f; hbuf[1][tid & 31] = 0.0f; }
    {   // zero zbuf (128 floats / 96 threads)
        zbuf[0][0] = 0.0f;  // keep compiler honest; full init below
    }
    for (int idx = tid; idx < 128; idx += 96) ((float*)zbuf)[idx] = 0.0f;

    // ---- per-lane weights ----
    ull WA[8], WB[8];
    float biasA = 0.f, biasB = 0.f, wxA = 0.f, wxB = 0.f;
    const int giA = hi * 16 + u;          // gate A row
    const int giB = (hi + 2) * 16 + u;    // gate B row

    if (w == 0) {                 // layer0 recurrent rows
        const ull* Wp = (const ull*)Whh0;
#pragma unroll
        for (int k = 0; k < 8; k++) { WA[k] = Wp[giA * 8 + k]; WB[k] = Wp[giB * 8 + k]; }
        biasA = bih0[giA] + bhh0[giA];  biasB = bih0[giB] + bhh0[giB];
        wxA = Wih0[giA];                wxB = Wih0[giB];
    } else if (w == 1) {          // layer1 recurrent rows
        const ull* Wp = (const ull*)Whh1;
#pragma unroll
        for (int k = 0; k < 8; k++) { WA[k] = Wp[giA * 8 + k]; WB[k] = Wp[giB * 8 + k]; }
    } else {                      // w == 2: layer1 input rows (+ layer1 biases)
        const ull* Wp = (const ull*)Wih1;
#pragma unroll
        for (int k = 0; k < 8; k++) { WA[k] = Wp[giA * 8 + k]; WB[k] = Wp[giB * 8 + k]; }
        biasA = bih1[giA] + bhh1[giA];  biasB = bih1[giB] + bhh1[giB];
    }
    // gate-B activation params (hi=0 -> tanh(g), hi=1 -> sigmoid(o))
    const float sB  = (hi == 0) ? 1.0f : 0.5f;
    const float pmB = (hi == 0) ? 1.0f : 0.5f;
    const float paB = (hi == 0) ? 0.0f : 0.5f;

    float h = 0.0f, c = 0.0f;

#pragma unroll 2
    for (int i = 0; i <= T_STEPS + 1; i++) {
        __syncthreads();
        const int p = i & 1;

        if (w == 0) {
            // ---- layer0 step i: gates over h0[i-1] = hbuf[p][0..15] ----
            const float xv = x_sh[(i < T_STEPS) ? i : 0];
            const ulonglong2* hp = (const ulonglong2*)hbuf[p];
            const ulonglong2 t0 = hp[0], t1 = hp[1], t2 = hp[2], t3 = hp[3];
            const ull op[8] = { t0.x, t0.y, t1.x, t1.y, t2.x, t2.y, t3.x, t3.y };

            ull a0 = ffma2(WA[0], op[0], pack2(fmaf(wxA, xv, biasA), 0.f));
            ull a1 = ffma2(WA[1], op[1], 0ull);
            ull b0 = ffma2(WB[0], op[0], pack2(fmaf(wxB, xv, biasB), 0.f));
            ull b1 = ffma2(WB[1], op[1], 0ull);
#pragma unroll
            for (int k = 2; k < 8; k += 2) {
                a0 = ffma2(WA[k], op[k], a0);  a1 = ffma2(WA[k + 1], op[k + 1], a1);
                b0 = ffma2(WB[k], op[k], b0);  b1 = ffma2(WB[k + 1], op[k + 1], b1);
            }
            const float aA = hsum2(fadd2(a0, a1));
            const float aB = hsum2(fadd2(b0, b1));
            const float vA = sigapx(aA);                        // i or f
            const float vB = fmaf(pmB, tanhapx(sB * aB), paB);  // g or o
            const float fv = __shfl_sync(0xffffffffu, vA, lane | 16);
            const float ov = __shfl_sync(0xffffffffu, vB, lane | 16);
            if (hi == 0 && i < T_STEPS) {
                c = fmaf(fv, c, vA * vB);
                h = ov * tanhapx(c);
                hbuf[p ^ 1][u] = h;
            }
        } else if (w == 2) {
            // ---- z[i-1] = Wih1 * h0[i-1] + bias1 ----
            const ulonglong2* hp = (const ulonglong2*)hbuf[p];
            const ulonglong2 t0 = hp[0], t1 = hp[1], t2 = hp[2], t3 = hp[3];
            const ull op[8] = { t0.x, t0.y, t1.x, t1.y, t2.x, t2.y, t3.x, t3.y };

            ull a0 = ffma2(WA[0], op[0], pack2(biasA, 0.f));
            ull a1 = ffma2(WA[1], op[1], 0ull);
            ull b0 = ffma2(WB[0], op[0], pack2(biasB, 0.f));
            ull b1 = ffma2(WB[1], op[1], 0ull);
#pragma unroll
            for (int k = 2; k < 8; k += 2) {
                a0 = ffma2(WA[k], op[k], a0);  a1 = ffma2(WA[k + 1], op[k + 1], a1);
                b0 = ffma2(WB[k], op[k], b0);  b1 = ffma2(WB[k + 1], op[k + 1], b1);
            }
            zbuf[p ^ 1][giA] = hsum2(fadd2(a0, a1));
            zbuf[p ^ 1][giB] = hsum2(fadd2(b0, b1));
        } else {
            // ---- layer1 step i-2: gates = z[i-2] + Whh1 * h1[i-3] ----
            const float zA = zbuf[p][giA];
            const float zB = zbuf[p][giB];
            const ulonglong2* hp = (const ulonglong2*)(hbuf[p] + 16);
            const ulonglong2 t0 = hp[0], t1 = hp[1], t2 = hp[2], t3 = hp[3];
            const ull op[8] = { t0.x, t0.y, t1.x, t1.y, t2.x, t2.y, t3.x, t3.y };

            ull a0 = ffma2(WA[0], op[0], pack2(zA, 0.f));
            ull a1 = ffma2(WA[1], op[1], 0ull);
            ull b0 = ffma2(WB[0], op[0], pack2(zB, 0.f));
            ull b1 = ffma2(WB[1], op[1], 0ull);
#pragma unroll
            for (int k = 2; k < 8; k += 2) {
                a0 = ffma2(WA[k], op[k], a0);  a1 = ffma2(WA[k + 1], op[k + 1], a1);
                b0 = ffma2(WB[k], op[k], b0);  b1 = ffma2(WB[k + 1], op[k + 1], b1);
            }
            const float aA = hsum2(fadd2(a0, a1));
            const float aB = hsum2(fadd2(b0, b1));
            const float vA = sigapx(aA);
            const float vB = fmaf(pmB, tanhapx(sB * aB), paB);
            const float fv = __shfl_sync(0xffffffffu, vA, lane | 16);
            const float ov = __shfl_sync(0xffffffffu, vB, lane | 16);
            if (hi == 0 && i >= 2) {
                c = fmaf(fv, c, vA * vB);
                h = ov * tanhapx(c);
                hbuf[p ^ 1][16 + u] = h;
                g_h2[(i - 2) * 16 + u] = h;
            }
        }
    }
}

// MLP 16 -> 64 (relu) -> 32 (relu) -> 1. One warp per timestep (512 blocks).
__global__ void __launch_bounds__(32) mlp_kernel(
    const float* __restrict__ W1, const float* __restrict__ b1,
    const float* __restrict__ W2, const float* __restrict__ b2,
    const float* __restrict__ W3, const float* __restrict__ b3,
    float* __restrict__ out)
{
    __shared__ __align__(16) float z1sh[64];
    const int t = blockIdx.x, lane = threadIdx.x;

    const float4* hp = (const float4*)(g_h2 + t * 16);
    const float4 h4[4] = { hp[0], hp[1], hp[2], hp[3] };

    float acc0 = b1[lane], acc1 = b1[lane + 32];
    const float4* w1a = (const float4*)(W1 + lane * 16);
    const float4* w1b = (const float4*)(W1 + (lane + 32) * 16);
#pragma unroll
    for (int q = 0; q < 4; q++) {
        const float4 wa = w1a[q], wb = w1b[q], hq = h4[q];
        acc0 = fmaf(wa.x, hq.x, acc0); acc0 = fmaf(wa.y, hq.y, acc0);
        acc0 = fmaf(wa.z, hq.z, acc0); acc0 = fmaf(wa.w, hq.w, acc0);
        acc1 = fmaf(wb.x, hq.x, acc1); acc1 = fmaf(wb.y, hq.y, acc1);
        acc1 = fmaf(wb.z, hq.z, acc1); acc1 = fmaf(wb.w, hq.w, acc1);
    }
    z1sh[lane]      = fmaxf(acc0, 0.0f);
    z1sh[lane + 32] = fmaxf(acc1, 0.0f);
    __syncwarp();

    float a2 = b2[lane];
    const float4* w2p = (const float4*)(W2 + lane * 64);
    const float4* z1p = (const float4*)z1sh;
#pragma unroll
    for (int q = 0; q < 16; q++) {
        const float4 wv = w2p[q], zv = z1p[q];
        a2 = fmaf(wv.x, zv.x, a2); a2 = fmaf(wv.y, zv.y, a2);
        a2 = fmaf(wv.z, zv.z, a2); a2 = fmaf(wv.w, zv.w, a2);
    }
    float v = fmaxf(a2, 0.0f) * W3[lane];
#pragma unroll
    for (int off = 16; off; off >>= 1)
        v += __shfl_xor_sync(0xffffffffu, v, off);
    if (lane == 0) out[t] = v + b3[0];
}

extern "C" void kernel_launch(void* const* d_in, const int* in_sizes, int n_in,
                              void* d_out, int out_size)
{
    const float* x    = (const float*)d_in[0];
    const float* Wih0 = (const float*)d_in[1];
    const float* Whh0 = (const float*)d_in[2];
    const float* bih0 = (const float*)d_in[3];
    const float* bhh0 = (const float*)d_in[4];
    const float* Wih1 = (const float*)d_in[5];
    const float* Whh1 = (const float*)d_in[6];
    const float* bih1 = (const float*)d_in[7];
    const float* bhh1 = (const float*)d_in[8];
    const float* W1   = (const float*)d_in[9];
    const float* b1   = (const float*)d_in[10];
    const float* W2   = (const float*)d_in[11];
    const float* b2   = (const float*)d_in[12];
    const float* W3   = (const float*)d_in[13];
    const float* b3   = (const float*)d_in[14];
    float* out = (float*)d_out;

    lstm_recur_kernel<<<1, 96>>>(x, Wih0, Whh0, bih0, bhh0,
                                 Wih1, Whh1, bih1, bhh1);
    mlp_kernel<<<T_STEPS, 32>>>(W1, b1, W2, b2, W3, b3, out);
}

// round 8
// speedup vs baseline: 2.5398x; 1.4545x over previous
#include <cuda_runtime.h>

#define T_STEPS 512
#define BATCH   4096
#define RING    128
#define RMASK   (RING - 1)
#define BLK     16
#define NBLK    (T_STEPS / BLK)   // 32
#define RBLK    (RING / BLK)      // 8

__device__ __align__(16) float g_h2[T_STEPS * 16];

typedef unsigned long long ull;

__device__ __forceinline__ ull ffma2(ull a, ull b, ull c) {
    ull d; asm("fma.rn.f32x2 %0, %1, %2, %3;" : "=l"(d) : "l"(a), "l"(b), "l"(c)); return d;
}
__device__ __forceinline__ ull fadd2(ull a, ull b) {
    ull d; asm("add.rn.f32x2 %0, %1, %2;" : "=l"(d) : "l"(a), "l"(b)); return d;
}
__device__ __forceinline__ float hsum2(ull a) {
    float lo, hi; asm("mov.b64 {%0, %1}, %2;" : "=f"(lo), "=f"(hi) : "l"(a)); return lo + hi;
}
__device__ __forceinline__ ull pack2(float lo, float hi) {
    ull d; asm("mov.b64 %0, {%1, %2};" : "=l"(d) : "f"(lo), "f"(hi)); return d;
}
__device__ __forceinline__ float tanhapx(float x) {
    float y; asm("tanh.approx.f32 %0, %1;" : "=f"(y) : "f"(x)); return y;
}
__device__ __forceinline__ float sigapx(float x) {       // 0.5*tanh(x/2)+0.5
    return fmaf(0.5f, tanhapx(0.5f * x), 0.5f);
}

__device__ __forceinline__ unsigned ld_acq(const unsigned* p) {
    unsigned v;
    asm volatile("ld.acquire.cta.b32 %0, [%1];" : "=r"(v) : "l"(p) : "memory");
    return v;
}
__device__ __forceinline__ void st_rel(unsigned* p, unsigned v) {
    asm volatile("st.release.cta.b32 [%0], %1;" :: "l"(p), "r"(v) : "memory");
}
__device__ __forceinline__ void wait_ge(const unsigned* p, unsigned tgt) {
    if (ld_acq(p) >= tgt) return;
    while (ld_acq(p) < tgt) __nanosleep(64);
}

// 96 threads, 3 free-running warps (no block barrier in the main loops):
//   warp0: layer0 step j   (self-recurrent; publishes h0 ring)
//   warp2: z[j] = Wih1*h0[j] + bias1  (h0 ring -> z ring; pure throughput)
//   warp1: layer1 step j   (z ring + own h1; writes g_h2)
// Visibility via per-16-step-block release/acquire counters; rings hold 128
// steps so backpressure never triggers in steady state.
// Lane scheme (all warps): lane = u + 16*hi; gate A = hi ({i,f}), gate B =
// hi+2 ({g,o}); hi=0 lanes own (c,h) of unit u.
__global__ void __launch_bounds__(96, 1) lstm_recur_kernel(
    const float* __restrict__ x,
    const float* __restrict__ Wih0, const float* __restrict__ Whh0,
    const float* __restrict__ bih0, const float* __restrict__ bhh0,
    const float* __restrict__ Wih1, const float* __restrict__ Whh1,
    const float* __restrict__ bih1, const float* __restrict__ bhh1)
{
    __shared__ float x_sh[T_STEPS];
    __shared__ __align__(16) float h0ring[RING][16];
    __shared__ __align__(16) float zring[RING][64];
    __shared__ __align__(16) float h1buf[2][16];
    __shared__ unsigned cnt[3];   // [0]=c0 (w0 blocks), [1]=c2 (w2), [2]=c1 (w1)

    const int tid  = threadIdx.x;
    const int w    = tid >> 5;
    const int lane = tid & 31;
    const int u    = lane & 15;
    const int hi   = lane >> 4;

    // ---- init ----
#pragma unroll
    for (int r = 0; r < 6; r++) {
        const int idx = tid + 96 * r;
        if (idx < T_STEPS) x_sh[idx] = x[idx * BATCH + (BATCH - 1)];
    }
    if (tid < 16)  h0ring[RING - 1][tid] = 0.0f;   // h0[-1] = 0
    if (tid < 32)  ((float*)h1buf)[tid] = 0.0f;    // h1[-1] = 0
    if (tid < 3)   cnt[tid] = 0;

    // ---- per-lane weights ----
    const int giA = hi * 16 + u;
    const int giB = (hi + 2) * 16 + u;
    ull WA[8], WB[8];
    float biasA = 0.f, biasB = 0.f, wxA = 0.f, wxB = 0.f;
    if (w == 0) {
        const ull* Wp = (const ull*)Whh0;
#pragma unroll
        for (int k = 0; k < 8; k++) { WA[k] = Wp[giA * 8 + k]; WB[k] = Wp[giB * 8 + k]; }
        biasA = bih0[giA] + bhh0[giA];  biasB = bih0[giB] + bhh0[giB];
        wxA   = Wih0[giA];              wxB   = Wih0[giB];
    } else if (w == 2) {
        const ull* Wp = (const ull*)Wih1;
#pragma unroll
        for (int k = 0; k < 8; k++) { WA[k] = Wp[giA * 8 + k]; WB[k] = Wp[giB * 8 + k]; }
        biasA = bih1[giA] + bhh1[giA];  biasB = bih1[giB] + bhh1[giB];
    } else {
        const ull* Wp = (const ull*)Whh1;
#pragma unroll
        for (int k = 0; k < 8; k++) { WA[k] = Wp[giA * 8 + k]; WB[k] = Wp[giB * 8 + k]; }
    }
    const float sB  = (hi == 0) ? 1.0f : 0.5f;   // gate B: tanh(g) vs sigmoid(o)
    const float pmB = (hi == 0) ? 1.0f : 0.5f;
    const float paB = (hi == 0) ? 0.0f : 0.5f;

    __syncthreads();   // the ONLY block-wide barrier

    if (w == 0) {
        // ================= layer0 =================
        float h = 0.f, c = 0.f;
        for (int b = 0; b < NBLK; b++) {
            if (b >= RBLK) { wait_ge(&cnt[1], b - RBLK + 1); __syncwarp(); }
#pragma unroll 2
            for (int jj = 0; jj < BLK; jj++) {
                const int j = b * BLK + jj;
                __syncwarp();
                const ulonglong2* hp = (const ulonglong2*)h0ring[(j + RING - 1) & RMASK];
                const ulonglong2 t0 = hp[0], t1 = hp[1], t2 = hp[2], t3 = hp[3];
                const ull op[8] = { t0.x, t0.y, t1.x, t1.y, t2.x, t2.y, t3.x, t3.y };
                const float xv = x_sh[j];

                ull a0 = ffma2(WA[0], op[0], pack2(fmaf(wxA, xv, biasA), 0.f));
                ull a1 = ffma2(WA[1], op[1], 0ull);
                ull b0 = ffma2(WB[0], op[0], pack2(fmaf(wxB, xv, biasB), 0.f));
                ull b1 = ffma2(WB[1], op[1], 0ull);
#pragma unroll
                for (int k = 2; k < 8; k += 2) {
                    a0 = ffma2(WA[k], op[k], a0);  a1 = ffma2(WA[k + 1], op[k + 1], a1);
                    b0 = ffma2(WB[k], op[k], b0);  b1 = ffma2(WB[k + 1], op[k + 1], b1);
                }
                const float aA = hsum2(fadd2(a0, a1));
                const float aB = hsum2(fadd2(b0, b1));
                const float vA = sigapx(aA);                        // i | f
                const float vB = fmaf(pmB, tanhapx(sB * aB), paB);  // g | o
                const float fv = __shfl_sync(0xffffffffu, vA, lane | 16);
                const float ov = __shfl_sync(0xffffffffu, vB, lane | 16);
                c = fmaf(fv, c, vA * vB);            // garbage on hi=1 lanes (ok)
                h = ov * tanhapx(c);
                if (hi == 0) h0ring[j & RMASK][u] = h;
            }
            __syncwarp();
            if (lane == 0) st_rel(&cnt[0], b + 1);
        }
    } else if (w == 2) {
        // ================= z = Wih1*h0 + bias1 =================
        for (int b = 0; b < NBLK; b++) {
            wait_ge(&cnt[0], b + 1);
            if (b >= RBLK) wait_ge(&cnt[2], b - RBLK + 1);
            __syncwarp();
#pragma unroll 4
            for (int jj = 0; jj < BLK; jj++) {
                const int j = b * BLK + jj;
                const ulonglong2* hp = (const ulonglong2*)h0ring[j & RMASK];
                const ulonglong2 t0 = hp[0], t1 = hp[1], t2 = hp[2], t3 = hp[3];
                const ull op[8] = { t0.x, t0.y, t1.x, t1.y, t2.x, t2.y, t3.x, t3.y };

                ull a0 = ffma2(WA[0], op[0], pack2(biasA, 0.f));
                ull a1 = ffma2(WA[1], op[1], 0ull);
                ull b0 = ffma2(WB[0], op[0], pack2(biasB, 0.f));
                ull b1 = ffma2(WB[1], op[1], 0ull);
#pragma unroll
                for (int k = 2; k < 8; k += 2) {
                    a0 = ffma2(WA[k], op[k], a0);  a1 = ffma2(WA[k + 1], op[k + 1], a1);
                    b0 = ffma2(WB[k], op[k], b0);  b1 = ffma2(WB[k + 1], op[k + 1], b1);
                }
                zring[j & RMASK][giA] = hsum2(fadd2(a0, a1));
                zring[j & RMASK][giB] = hsum2(fadd2(b0, b1));
            }
            __syncwarp();
            if (lane == 0) st_rel(&cnt[1], b + 1);
        }
    } else {
        // ================= layer1 =================
        float h = 0.f, c = 0.f;
        for (int b = 0; b < NBLK; b++) {
            wait_ge(&cnt[1], b + 1);
            __syncwarp();
#pragma unroll 2
            for (int jj = 0; jj < BLK; jj++) {
                const int j = b * BLK + jj;
                __syncwarp();
                const ulonglong2* hp = (const ulonglong2*)h1buf[j & 1];
                const ulonglong2 t0 = hp[0], t1 = hp[1], t2 = hp[2], t3 = hp[3];
                const ull op[8] = { t0.x, t0.y, t1.x, t1.y, t2.x, t2.y, t3.x, t3.y };
                const float zA = zring[j & RMASK][giA];
                const float zB = zring[j & RMASK][giB];

                ull a0 = ffma2(WA[0], op[0], pack2(zA, 0.f));
                ull a1 = ffma2(WA[1], op[1], 0ull);
                ull b0 = ffma2(WB[0], op[0], pack2(zB, 0.f));
                ull b1 = ffma2(WB[1], op[1], 0ull);
#pragma unroll
                for (int k = 2; k < 8; k += 2) {
                    a0 = ffma2(WA[k], op[k], a0);  a1 = ffma2(WA[k + 1], op[k + 1], a1);
                    b0 = ffma2(WB[k], op[k], b0);  b1 = ffma2(WB[k + 1], op[k + 1], b1);
                }
                const float aA = hsum2(fadd2(a0, a1));
                const float aB = hsum2(fadd2(b0, b1));
                const float vA = sigapx(aA);
                const float vB = fmaf(pmB, tanhapx(sB * aB), paB);
                const float fv = __shfl_sync(0xffffffffu, vA, lane | 16);
                const float ov = __shfl_sync(0xffffffffu, vB, lane | 16);
                c = fmaf(fv, c, vA * vB);
                h = ov * tanhapx(c);
                if (hi == 0) {
                    h1buf[(j + 1) & 1][u] = h;
                    g_h2[j * 16 + u] = h;
                }
            }
            __syncwarp();
            if (lane == 0) st_rel(&cnt[2], b + 1);
        }
    }
}

// MLP 16 -> 64 (relu) -> 32 (relu) -> 1. One warp per timestep (512 blocks).
__global__ void __launch_bounds__(32) mlp_kernel(
    const float* __restrict__ W1, const float* __restrict__ b1,
    const float* __restrict__ W2, const float* __restrict__ b2,
    const float* __restrict__ W3, const float* __restrict__ b3,
    float* __restrict__ out)
{
    __shared__ __align__(16) float z1sh[64];
    const int t = blockIdx.x, lane = threadIdx.x;

    const float4* hp = (const float4*)(g_h2 + t * 16);
    const float4 h4[4] = { hp[0], hp[1], hp[2], hp[3] };

    float acc0 = b1[lane], acc1 = b1[lane + 32];
    const float4* w1a = (const float4*)(W1 + lane * 16);
    const float4* w1b = (const float4*)(W1 + (lane + 32) * 16);
#pragma unroll
    for (int q = 0; q < 4; q++) {
        const float4 wa = w1a[q], wb = w1b[q], hq = h4[q];
        acc0 = fmaf(wa.x, hq.x, acc0); acc0 = fmaf(wa.y, hq.y, acc0);
        acc0 = fmaf(wa.z, hq.z, acc0); acc0 = fmaf(wa.w, hq.w, acc0);
        acc1 = fmaf(wb.x, hq.x, acc1); acc1 = fmaf(wb.y, hq.y, acc1);
        acc1 = fmaf(wb.z, hq.z, acc1); acc1 = fmaf(wb.w, hq.w, acc1);
    }
    z1sh[lane]      = fmaxf(acc0, 0.0f);
    z1sh[lane + 32] = fmaxf(acc1, 0.0f);
    __syncwarp();

    float a2 = b2[lane];
    const float4* w2p = (const float4*)(W2 + lane * 64);
    const float4* z1p = (const float4*)z1sh;
#pragma unroll
    for (int q = 0; q < 16; q++) {
        const float4 wv = w2p[q], zv = z1p[q];
        a2 = fmaf(wv.x, zv.x, a2); a2 = fmaf(wv.y, zv.y, a2);
        a2 = fmaf(wv.z, zv.z, a2); a2 = fmaf(wv.w, zv.w, a2);
    }
    float v = fmaxf(a2, 0.0f) * W3[lane];
#pragma unroll
    for (int off = 16; off; off >>= 1)
        v += __shfl_xor_sync(0xffffffffu, v, off);
    if (lane == 0) out[t] = v + b3[0];
}

extern "C" void kernel_launch(void* const* d_in, const int* in_sizes, int n_in,
                              void* d_out, int out_size)
{
    const float* x    = (const float*)d_in[0];
    const float* Wih0 = (const float*)d_in[1];
    const float* Whh0 = (const float*)d_in[2];
    const float* bih0 = (const float*)d_in[3];
    const float* bhh0 = (const float*)d_in[4];
    const float* Wih1 = (const float*)d_in[5];
    const float* Whh1 = (const float*)d_in[6];
    const float* bih1 = (const float*)d_in[7];
    const float* bhh1 = (const float*)d_in[8];
    const float* W1   = (const float*)d_in[9];
    const float* b1   = (const float*)d_in[10];
    const float* W2   = (const float*)d_in[11];
    const float* b2   = (const float*)d_in[12];
    const float* W3   = (const float*)d_in[13];
    const float* b3   = (const float*)d_in[14];
    float* out = (float*)d_out;

    lstm_recur_kernel<<<1, 96>>>(x, Wih0, Whh0, bih0, bhh0,
                                 Wih1, Whh1, bih1, bhh1);
    mlp_kernel<<<T_STEPS, 32>>>(W1, b1, W2, b2, W3, b3, out);
}